// round 13
// baseline (speedup 1.0000x reference)
#include <cuda_runtime.h>
#include <cuda_fp16.h>
#include <math.h>
#include <stdint.h>

// ---------------- problem constants ----------------
#define BS      2
#define NQ      40000
#define NV      40000
#define EMBED   256
#define HEADS   8
#define POINTS  4
#define HEAD_DIM 32
#define SH      200
#define SW      200
#define MROWS   (BS * NQ)      // 80000

// ---------------- device scratch ----------------
__device__ float  g_v   [(size_t)BS * NV * EMBED];       // projected value (fp32)
__device__ float  g_oa  [(size_t)BS * NQ * 96];          // fused [off(64) | attn(32)]
__device__ __half g_tmp [(size_t)BS * NQ * EMBED];       // sampled output (fp16)
__device__ float  g_boa [96];
// transposed weights: [N][K] fp16
__device__ __half g_Wv [256 * 256];
__device__ __half g_Wo [256 * 256];
__device__ __half g_Woa[ 96 * 256];

// ---------------- warp mma / ldmatrix helpers ----------------
__device__ __forceinline__ void mma_f16(float* d, const uint32_t* a, const uint32_t* b) {
    asm volatile(
        "mma.sync.aligned.m16n8k16.row.col.f32.f16.f16.f32 "
        "{%0,%1,%2,%3}, {%4,%5,%6,%7}, {%8,%9}, {%0,%1,%2,%3};"
        : "+f"(d[0]), "+f"(d[1]), "+f"(d[2]), "+f"(d[3])
        : "r"(a[0]), "r"(a[1]), "r"(a[2]), "r"(a[3]), "r"(b[0]), "r"(b[1]));
}
__device__ __forceinline__ void ldsm_x4(uint32_t& r0, uint32_t& r1, uint32_t& r2, uint32_t& r3,
                                        uint32_t addr) {
    asm volatile("ldmatrix.sync.aligned.m8n8.x4.shared.b16 {%0,%1,%2,%3}, [%4];"
                 : "=r"(r0), "=r"(r1), "=r"(r2), "=r"(r3) : "r"(addr));
}
__device__ __forceinline__ void ldsm_x2(uint32_t& r0, uint32_t& r1, uint32_t addr) {
    asm volatile("ldmatrix.sync.aligned.m8n8.x2.shared.b16 {%0,%1}, [%2];"
                 : "=r"(r0), "=r"(r1) : "r"(addr));
}
__device__ __forceinline__ uint32_t cvt_f16x2(float hi, float lo) {
    uint32_t r;
    asm("cvt.rn.f16x2.f32 %0, %1, %2;" : "=r"(r) : "f"(hi), "f"(lo));
    return r;
}

// ---------------- merged weight transpose to fp16 ----------------
__global__ void convert_all_kernel(const float* __restrict__ Wv, const float* __restrict__ Wo,
                                   const float* __restrict__ Woff, const float* __restrict__ boff,
                                   const float* __restrict__ Wattn, const float* __restrict__ battn,
                                   __half* __restrict__ dWv, __half* __restrict__ dWo,
                                   __half* __restrict__ dWoa, float* __restrict__ bcomb)
{
    int idx = blockIdx.x * 256 + threadIdx.x;
    if (idx < 65536) {
        int n = idx >> 8, k = idx & 255;
        dWv[idx] = __float2half_rn(Wv[k * 256 + n]);
    } else if (idx < 131072) {
        int j = idx - 65536;
        int n = j >> 8, k = j & 255;
        dWo[j] = __float2half_rn(Wo[k * 256 + n]);
    } else if (idx < 131072 + 24576) {
        int j = idx - 131072;
        int n = j >> 8, k = j & 255;
        float v = (n < 64) ? Woff[k * 64 + n] : Wattn[k * 32 + (n - 64)];
        dWoa[j] = __float2half_rn(v);
        if (j < 96) bcomb[j] = (j < 64) ? boff[j] : battn[j - 64];
    }
}

// ---------------- fp16 HMMA GEMM body: single pass, BK=128, ldmatrix loads ----------------
template<int BN, bool RES, typename AT>
__device__ __forceinline__ void gemm_body(const AT* __restrict__ A,
                                          const __half* __restrict__ Bt,
                                          const float* __restrict__ bias,
                                          const float* __restrict__ res,
                                          float* __restrict__ C, int ldC,
                                          int nBlk, int bm)
{
    constexpr int K = 256, BK = 128, BM = 128;
    constexpr int WN  = 4;
    constexpr int WTN = BN / WN;
    constexpr int MT  = 4;
    constexpr int NTI = WTN / 8;
    constexpr int NPAIR = NTI / 2;
    constexpr int AST = 272;               // bytes per 128-fp16 row (256 + 16 pad)
    constexpr int A_0 = 0;
    constexpr int B_0 = BM * AST;

    extern __shared__ char sm[];
    const uint32_t smBase = (uint32_t)__cvta_generic_to_shared(sm);

    const int tid  = threadIdx.x;
    const int wid  = tid >> 5;
    const int lane = tid & 31;
    const int g    = lane >> 2;
    const int c    = lane & 3;
    const int wm   = wid / WN;
    const int wn   = wid % WN;
    const int wmBase = wm * 64;
    const int wnBase = wn * WTN;
    const int nOff = nBlk * BN;

    float acc[MT][NTI][4];
#pragma unroll
    for (int i = 0; i < MT; i++)
#pragma unroll
        for (int j = 0; j < NTI; j++)
#pragma unroll
            for (int q = 0; q < 4; q++) acc[i][j][q] = 0.f;

    const int aRow = wmBase + (lane & 15);
    const int aKs  = (lane >> 4) * 16;
    const int bRow = wnBase + ((lane >> 4) << 3) + (lane & 7);
    const int bKs  = ((lane >> 3) & 1) * 16;
    const uint32_t aB = smBase + (uint32_t)(A_0 + aRow * AST + aKs);
    const uint32_t bB = smBase + (uint32_t)(B_0 + bRow * AST + bKs);

    for (int it = 0; it < K / BK; it++) {
        const int k0 = it * BK;
        if constexpr (sizeof(AT) == 4) {
#pragma unroll
            for (int f = tid; f < BM * 32; f += 256) {
                const int r = f >> 5, c4 = f & 31;
                float4 a = *reinterpret_cast<const float4*>(
                    &A[(size_t)(bm * BM + r) * K + k0 + c4 * 4]);
                uint2 v;
                v.x = cvt_f16x2(a.y, a.x);
                v.y = cvt_f16x2(a.w, a.z);
                *reinterpret_cast<uint2*>(sm + A_0 + r * AST + c4 * 8) = v;
            }
        } else {
#pragma unroll
            for (int f = tid; f < BM * 16; f += 256) {
                const int r = f >> 4, cu = f & 15;
                uint4 w = *reinterpret_cast<const uint4*>(
                    &A[(size_t)(bm * BM + r) * K + k0 + cu * 8]);
                *reinterpret_cast<uint4*>(sm + A_0 + r * AST + cu * 16) = w;
            }
        }
#pragma unroll
        for (int f = tid; f < BN * 16; f += 256) {
            const int n = f >> 4, cu = f & 15;
            uint4 w = *reinterpret_cast<const uint4*>(&Bt[(nOff + n) * K + k0 + cu * 8]);
            *reinterpret_cast<uint4*>(sm + B_0 + n * AST + cu * 16) = w;
        }
        __syncthreads();

#pragma unroll
        for (int ks = 0; ks < BK / 16; ks++) {
            const uint32_t kb = ks * 32;
            uint32_t af[MT][4], bf[NTI][2];
#pragma unroll
            for (int p = 0; p < NPAIR; p++)
                ldsm_x4(bf[2*p][0], bf[2*p][1], bf[2*p+1][0], bf[2*p+1][1],
                        bB + (uint32_t)(p * 16 * AST) + kb);
            if (NTI & 1)
                ldsm_x2(bf[NTI-1][0], bf[NTI-1][1],
                        bB + (uint32_t)((NTI-1) * 8 * AST) + kb);
#pragma unroll
            for (int mi = 0; mi < MT; mi++)
                ldsm_x4(af[mi][0], af[mi][1], af[mi][2], af[mi][3],
                        aB + (uint32_t)(mi * 16 * AST) + kb);
#pragma unroll
            for (int mi = 0; mi < MT; mi++)
#pragma unroll
                for (int ni = 0; ni < NTI; ni++)
                    mma_f16(acc[mi][ni], af[mi], bf[ni]);
        }
        __syncthreads();
    }

#pragma unroll
    for (int mi = 0; mi < MT; mi++) {
        const int row0 = bm * BM + wmBase + mi * 16 + g;
#pragma unroll
        for (int ni = 0; ni < NTI; ni++) {
            const int col = nOff + wnBase + ni * 8 + c * 2;
            float2 bb = *reinterpret_cast<const float2*>(&bias[col]);
            float2 o0, o1;
            o0.x = acc[mi][ni][0] + bb.x;
            o0.y = acc[mi][ni][1] + bb.y;
            o1.x = acc[mi][ni][2] + bb.x;
            o1.y = acc[mi][ni][3] + bb.y;
            if constexpr (RES) {
                float2 r0 = *reinterpret_cast<const float2*>(&res[(size_t)row0 * ldC + col]);
                float2 r1 = *reinterpret_cast<const float2*>(&res[(size_t)(row0 + 8) * ldC + col]);
                o0.x += r0.x; o0.y += r0.y;
                o1.x += r1.x; o1.y += r1.y;
            }
            *reinterpret_cast<float2*>(&C[(size_t)row0 * ldC + col]) = o0;
            *reinterpret_cast<float2*>(&C[(size_t)(row0 + 8) * ldC + col]) = o1;
        }
    }
}

// fused gemm1 (value proj, N=256 in 2 col-blocks) + gemm_oa (N=96): one launch
__global__ void __launch_bounds__(256, 2)
gemm_fused_kernel(const float* __restrict__ value, const __half* __restrict__ Wv,
                  const float* __restrict__ b_value, float* __restrict__ v_out,
                  const float* __restrict__ query, const __half* __restrict__ Woa,
                  const float* __restrict__ b_oa, float* __restrict__ oa_out)
{
    if (blockIdx.x < 2)
        gemm_body<128, false, float>(value, Wv, b_value, nullptr, v_out, 256,
                                     blockIdx.x, blockIdx.y);
    else
        gemm_body<96, false, float>(query, Woa, b_oa, nullptr, oa_out, 96,
                                    0, blockIdx.y);
}

// gemm3: out = tmp(fp16) @ W_out + b_out + query
__global__ void __launch_bounds__(256, 2)
gemm3_kernel(const __half* __restrict__ A, const __half* __restrict__ Bt,
             const float* __restrict__ bias, const float* __restrict__ res,
             float* __restrict__ C)
{
    gemm_body<128, true, __half>(A, Bt, bias, res, C, 256, blockIdx.x, blockIdx.y);
}

// ---------------- sampling v5: smem geometry + single-line gathers ----------------
// Block = 256 threads = 8 queries. Phase 1: thread t computes geometry for
// tuple (q=t>>5, h=(t>>2)&7, p=t&3) -> smem. Phase 2: warp w = query q0+w,
// per head: broadcast-LDS geometry, 16 one-line LDG.32 (lane = channel), FMA.
__global__ void __launch_bounds__(256)
sample_kernel(const float* __restrict__ refp, const float* __restrict__ oa,
              __half* __restrict__ outp)
{
    __shared__ int4   s_idx[256];
    __shared__ float4 s_w  [256];

    const int tid  = threadIdx.x;
    const int lane = tid & 31;
    const int wid  = tid >> 5;
    const int q0   = blockIdx.x * 8;

    // ---- phase 1: geometry ----
    {
        const int qq = tid >> 5;
        const int hh = (tid >> 2) & 7;
        const int p  = tid & 3;
        const int bq = q0 + qq;
        const float* oabase = oa + (size_t)bq * 96;

        float aw = oabase[64 + hh * 4 + p];
        float ox = oabase[hh * 8 + 2 * p];
        float oy = oabase[hh * 8 + 2 * p + 1];

        float m = fmaxf(aw, __shfl_xor_sync(0xffffffffu, aw, 1));
        m = fmaxf(m, __shfl_xor_sync(0xffffffffu, m, 2));
        float e = __expf(aw - m);
        float s = e + __shfl_xor_sync(0xffffffffu, e, 1);
        s = s + __shfl_xor_sync(0xffffffffu, s, 2);
        const float wp = e / s;

        const float rx = refp[(size_t)bq * 2 + 0];
        const float ry = refp[(size_t)bq * 2 + 1];

        float locx = rx + ox * (1.f / (float)SW);
        float locy = ry + oy * (1.f / (float)SH);
        float gx = 2.f * locx - 1.f;
        float gy = 2.f * locy - 1.f;
        float px = ((gx + 1.f) * (float)SW - 1.f) * 0.5f;
        float py = ((gy + 1.f) * (float)SH - 1.f) * 0.5f;
        float x0f = floorf(px), y0f = floorf(py);
        int   x0 = (int)x0f,    y0 = (int)y0f;
        float fx = px - x0f,    fy = py - y0f;

        const bool xv0 = (x0 >= 0)     && (x0 <= SW - 1);
        const bool xv1 = (x0 + 1 >= 0) && (x0 + 1 <= SW - 1);
        const bool yv0 = (y0 >= 0)     && (y0 <= SH - 1);
        const bool yv1 = (y0 + 1 >= 0) && (y0 + 1 <= SH - 1);

        int xc0 = min(max(x0, 0), SW - 1);
        int xc1 = min(max(x0 + 1, 0), SW - 1);
        int yc0 = min(max(y0, 0), SH - 1);
        int yc1 = min(max(y0 + 1, 0), SH - 1);

        float4 w4;
        w4.x = (xv0 && yv0) ? wp * (1.f - fx) * (1.f - fy) : 0.f;
        w4.y = (xv1 && yv0) ? wp * fx * (1.f - fy)         : 0.f;
        w4.z = (xv0 && yv1) ? wp * (1.f - fx) * fy         : 0.f;
        w4.w = (xv1 && yv1) ? wp * fx * fy                 : 0.f;

        int4 i4;
        i4.x = (yc0 * SW + xc0) * EMBED;
        i4.y = (yc0 * SW + xc1) * EMBED;
        i4.z = (yc1 * SW + xc0) * EMBED;
        i4.w = (yc1 * SW + xc1) * EMBED;

        s_idx[tid] = i4;
        s_w  [tid] = w4;
    }
    __syncthreads();

    // ---- phase 2: gathers; warp wid owns query q0+wid, lane = channel ----
    const int bq = q0 + wid;
    const int b  = bq / NQ;
    const float* vb0 = g_v + (size_t)b * NV * EMBED + lane;
    __half* outb = outp + (size_t)bq * EMBED + lane;

#pragma unroll
    for (int h = 0; h < HEADS; h++) {
        const int t = wid * 32 + h * 4;
        const float* vb = vb0 + h * HEAD_DIM;
        float acc = 0.f;
#pragma unroll
        for (int p = 0; p < POINTS; p++) {
            int4   ii = s_idx[t + p];
            float4 ww = s_w  [t + p];
            acc = fmaf(ww.x, vb[ii.x], acc);
            acc = fmaf(ww.y, vb[ii.y], acc);
            acc = fmaf(ww.z, vb[ii.z], acc);
            acc = fmaf(ww.w, vb[ii.w], acc);
        }
        outb[h * HEAD_DIM] = __float2half_rn(acc);
    }
}

// ---------------- launch ----------------
extern "C" void kernel_launch(void* const* d_in, const int* in_sizes, int n_in,
                              void* d_out, int out_size)
{
    const float* query   = (const float*)d_in[0];
    const float* value   = (const float*)d_in[1];
    const float* refpts  = (const float*)d_in[2];
    const float* W_value = (const float*)d_in[4];
    const float* b_value = (const float*)d_in[5];
    const float* W_off   = (const float*)d_in[6];
    const float* b_off   = (const float*)d_in[7];
    const float* W_attn  = (const float*)d_in[8];
    const float* b_attn  = (const float*)d_in[9];
    const float* W_out   = (const float*)d_in[10];
    const float* b_out   = (const float*)d_in[11];
    float* out = (float*)d_out;

    float *pv, *poa, *pboa;
    __half *ptmp, *wv, *wo, *woa;
    cudaGetSymbolAddress((void**)&pv,   g_v);
    cudaGetSymbolAddress((void**)&poa,  g_oa);
    cudaGetSymbolAddress((void**)&ptmp, g_tmp);
    cudaGetSymbolAddress((void**)&pboa, g_boa);
    cudaGetSymbolAddress((void**)&wv,   g_Wv);
    cudaGetSymbolAddress((void**)&wo,   g_Wo);
    cudaGetSymbolAddress((void**)&woa,  g_Woa);

    const int SMEM_128 = (128 + 128) * 272; // 69632
    cudaFuncSetAttribute(gemm_fused_kernel, cudaFuncAttributeMaxDynamicSharedMemorySize, SMEM_128);
    cudaFuncSetAttribute(gemm3_kernel,      cudaFuncAttributeMaxDynamicSharedMemorySize, SMEM_128);

    // merged weight transpose to fp16
    convert_all_kernel<<<(131072 + 24576 + 255) / 256, 256>>>(
        W_value, W_out, W_off, b_off, W_attn, b_attn, wv, wo, woa, pboa);

    const int GRID = MROWS / 128; // 625

    // 1+2+3 fused: v = value@Wv + b (x-blocks 0,1)  and  oa = query@Woa + b (x-block 2)
    gemm_fused_kernel<<<dim3(3, GRID), 256, SMEM_128>>>(
        value, wv, b_value, pv, query, woa, pboa, poa);
    // 4) softmax + bilinear sample -> fp16 tmp
    sample_kernel<<<MROWS / 8, 256>>>(refpts, poa, ptmp);
    // 5) out = tmp(fp16) @ W_out + b_out + query
    gemm3_kernel<<<dim3(2, GRID), 256, SMEM_128>>>(ptmp, wo, b_out, query, out);
}